// round 8
// baseline (speedup 1.0000x reference)
#include <cuda_runtime.h>
#include <cuda_bf16.h>
#include <cstdint>

#define BATCH 4
#define C_IN 256
#define C_MID 128
#define NSP 4096
#define INVN (1.0f/4096.0f)

typedef __nv_bfloat16 bf16;
typedef __nv_bfloat162 bf162;

// ---------------------------------------------------------------------------
// Device scratch
// ---------------------------------------------------------------------------
__device__ __align__(256) bf16  d_Tph[BATCH * C_MID * NSP];
__device__ __align__(256) bf16  d_Tg [BATCH * C_MID * NSP];
__device__ __align__(256) bf16  d_Xbf[BATCH * C_IN * NSP];   // X in bf16
__device__ __align__(256) float d_M  [BATCH * C_MID * C_MID];
__device__ __align__(256) float d_gs [BATCH * C_MID];
__device__ __align__(256) float d_ws [BATCH * C_MID];
__device__ __align__(256) bf16  d_Af [BATCH * C_IN * C_IN];
__device__ __align__(256) float d_cvec[BATCH * C_IN];

// ---------------------------------------------------------------------------
// Helpers
// ---------------------------------------------------------------------------
__device__ __forceinline__ void mma_bf16(float c[4], const uint32_t a[4],
                                         uint32_t b0, uint32_t b1) {
    asm volatile("mma.sync.aligned.m16n8k16.row.col.f32.bf16.bf16.f32 "
                 "{%0,%1,%2,%3}, {%4,%5,%6,%7}, {%8,%9}, {%0,%1,%2,%3};"
                 : "+f"(c[0]), "+f"(c[1]), "+f"(c[2]), "+f"(c[3])
                 : "r"(a[0]), "r"(a[1]), "r"(a[2]), "r"(a[3]), "r"(b0), "r"(b1));
}

__device__ __forceinline__ void mma_tf32(float c[4],
                                         uint32_t a0, uint32_t a1, uint32_t a2, uint32_t a3,
                                         uint32_t b0, uint32_t b1) {
    asm volatile("mma.sync.aligned.m16n8k8.row.col.f32.tf32.tf32.f32 "
                 "{%0,%1,%2,%3}, {%4,%5,%6,%7}, {%8,%9}, {%0,%1,%2,%3};"
                 : "+f"(c[0]), "+f"(c[1]), "+f"(c[2]), "+f"(c[3])
                 : "r"(a0), "r"(a1), "r"(a2), "r"(a3), "r"(b0), "r"(b1));
}

__device__ __forceinline__ void ldsm4(uint32_t r[4], const bf16* p) {
    uint32_t addr = (uint32_t)__cvta_generic_to_shared(p);
    asm volatile("ldmatrix.sync.aligned.m8n8.x4.shared.b16 {%0,%1,%2,%3}, [%4];"
                 : "=r"(r[0]), "=r"(r[1]), "=r"(r[2]), "=r"(r[3]) : "r"(addr));
}
__device__ __forceinline__ void ldsm4t(uint32_t r[4], const bf16* p) {
    uint32_t addr = (uint32_t)__cvta_generic_to_shared(p);
    asm volatile("ldmatrix.sync.aligned.m8n8.x4.trans.shared.b16 {%0,%1,%2,%3}, [%4];"
                 : "=r"(r[0]), "=r"(r[1]), "=r"(r[2]), "=r"(r[3]) : "r"(addr));
}

__device__ __forceinline__ uint32_t fbits(float f) { return __float_as_uint(f); }
__device__ __forceinline__ float rtf(float f) {
    uint32_t u;
    asm("cvt.rna.tf32.f32 %0, %1;" : "=r"(u) : "f"(f));
    return __uint_as_float(u);
}
__device__ __forceinline__ float4 rtf4(float4 v) {
    return make_float4(rtf(v.x), rtf(v.y), rtf(v.z), rtf(v.w));
}
__device__ __forceinline__ uint2 f4_to_bf(float4 v) {
    bf162 lo = __floats2bfloat162_rn(v.x, v.y);
    bf162 hi = __floats2bfloat162_rn(v.z, v.w);
    uint2 r;
    r.x = *(uint32_t*)&lo;
    r.y = *(uint32_t*)&hi;
    return r;
}
__device__ __forceinline__ float sum8bf(uint4 v) {
    const bf162* p = (const bf162*)&v;
    float s = 0.f;
#pragma unroll
    for (int i = 0; i < 4; i++) {
        float2 f = __bfloat1622float2(p[i]);
        s += f.x + f.y;
    }
    return s;
}
__device__ __forceinline__ float warp_dot128(const float* __restrict__ row,
                                             const float* __restrict__ v) {
    int lane = threadIdx.x & 31;
    float4 r0 = *(const float4*)(row + lane * 4);
    float4 v0 = *(const float4*)(v + lane * 4);
    float a = r0.x * v0.x + r0.y * v0.y + r0.z * v0.z + r0.w * v0.w;
#pragma unroll
    for (int o = 16; o; o >>= 1) a += __shfl_xor_sync(0xffffffffu, a, o);
    return a;
}

// ---------------------------------------------------------------------------
// proj: Tph = phi_w @ X, Tg = g_w @ X (bf16 TC, reg-prefetch pipeline),
// also emits d_Xbf (m0==0 CTAs). grid (33, 2, 4)
// ---------------------------------------------------------------------------
__global__ void __launch_bounds__(256) proj(const float* __restrict__ x,
                                            const float* __restrict__ phi_w,
                                            const float* __restrict__ g_w) {
    const int tid = threadIdx.x;
    if (blockIdx.x == 32) {
        const int sid = blockIdx.y * 4 + blockIdx.z;
        float4 z4 = make_float4(0, 0, 0, 0);
        float4* M4 = (float4*)d_M;
#pragma unroll
        for (int i = 0; i < 8; i++) M4[sid * 2048 + i * 256 + tid] = z4;
        if (sid == 0 && tid < 128) {
            ((float4*)d_gs)[tid] = z4;
            ((float4*)d_ws)[tid] = z4;
        }
        return;
    }

    __shared__ bf16 As1[64 * 40], As2[64 * 40], Bs[32 * 136];
    const int bz = blockIdx.z;
    const int m0 = blockIdx.y * 64;
    const int n0 = blockIdx.x * 128;
    const float* X = x + (size_t)bz * C_IN * NSP;
    bf16* Xbf = d_Xbf + (size_t)bz * C_IN * NSP;
    const bool do_xbf = (blockIdx.y == 0);

    const int lane = tid & 31, warp = tid >> 5;
    const int wm = warp >> 2, wn = warp & 3;
    const int gq = lane >> 2, tg = lane & 3;
    const int alr = tid >> 3, alc = (tid & 7) * 4;
    const int blr = tid >> 3, bf4 = (tid & 7);
    const int a_row = (lane & 7) + ((lane >> 3) & 1) * 8;
    const int a_col = (lane >> 4) * 8;
    const int bt_kr = (lane & 7) + ((lane >> 3) & 1) * 8;
    const int bt_nc = ((lane >> 4) & 1) * 8;

    float acc1[2][4][4] = {}, acc2[2][4][4] = {};

    float4 p0, p1, g0, g1, vb[4];
    // prologue loads (k0 = 0)
    p0 = *(const float4*)(phi_w + (size_t)(m0 + alr) * 256 + alc);
    p1 = *(const float4*)(phi_w + (size_t)(m0 + alr + 32) * 256 + alc);
    g0 = *(const float4*)(g_w + (size_t)(m0 + alr) * 256 + alc);
    g1 = *(const float4*)(g_w + (size_t)(m0 + alr + 32) * 256 + alc);
#pragma unroll
    for (int i = 0; i < 4; i++)
        vb[i] = *(const float4*)(X + (size_t)blr * NSP + n0 + (bf4 + 8 * i) * 4);

    for (int k0 = 0; k0 < 256; k0 += 32) {
        __syncthreads();
        *(uint2*)&As1[alr * 40 + alc] = f4_to_bf(p0);
        *(uint2*)&As1[(alr + 32) * 40 + alc] = f4_to_bf(p1);
        *(uint2*)&As2[alr * 40 + alc] = f4_to_bf(g0);
        *(uint2*)&As2[(alr + 32) * 40 + alc] = f4_to_bf(g1);
        uint2 xb[4];
#pragma unroll
        for (int i = 0; i < 4; i++) {
            xb[i] = f4_to_bf(vb[i]);
            *(uint2*)&Bs[blr * 136 + (bf4 + 8 * i) * 4] = xb[i];
        }
        if (do_xbf) {
#pragma unroll
            for (int i = 0; i < 4; i++)
                *(uint2*)(Xbf + (size_t)(k0 + blr) * NSP + n0 + (bf4 + 8 * i) * 4) = xb[i];
        }
        __syncthreads();

        if (k0 + 32 < 256) {
            int kn = k0 + 32;
            p0 = *(const float4*)(phi_w + (size_t)(m0 + alr) * 256 + kn + alc);
            p1 = *(const float4*)(phi_w + (size_t)(m0 + alr + 32) * 256 + kn + alc);
            g0 = *(const float4*)(g_w + (size_t)(m0 + alr) * 256 + kn + alc);
            g1 = *(const float4*)(g_w + (size_t)(m0 + alr + 32) * 256 + kn + alc);
#pragma unroll
            for (int i = 0; i < 4; i++)
                vb[i] = *(const float4*)(X + (size_t)(kn + blr) * NSP + n0 + (bf4 + 8 * i) * 4);
        }

#pragma unroll
        for (int kk = 0; kk < 32; kk += 16) {
            uint32_t a1[2][4], a2[2][4], bb[2][4];
#pragma unroll
            for (int ma = 0; ma < 2; ma++) {
                int rb = wm * 32 + ma * 16;
                ldsm4(a1[ma], &As1[(rb + a_row) * 40 + kk + a_col]);
                ldsm4(a2[ma], &As2[(rb + a_row) * 40 + kk + a_col]);
            }
#pragma unroll
            for (int pr = 0; pr < 2; pr++)
                ldsm4t(bb[pr], &Bs[(kk + bt_kr) * 136 + wn * 32 + pr * 16 + bt_nc]);
#pragma unroll
            for (int ma = 0; ma < 2; ma++)
#pragma unroll
                for (int na = 0; na < 4; na++) {
                    uint32_t b0 = bb[na >> 1][(na & 1) * 2];
                    uint32_t b1 = bb[na >> 1][(na & 1) * 2 + 1];
                    mma_bf16(acc1[ma][na], a1[ma], b0, b1);
                    mma_bf16(acc2[ma][na], a2[ma], b0, b1);
                }
        }
    }

    bf16* C1 = d_Tph + (size_t)bz * C_MID * NSP;
    bf16* C2 = d_Tg + (size_t)bz * C_MID * NSP;
#pragma unroll
    for (int ma = 0; ma < 2; ma++) {
        int rm = m0 + wm * 32 + ma * 16 + gq;
#pragma unroll
        for (int na = 0; na < 4; na++) {
            int cn = n0 + wn * 32 + na * 8 + 2 * tg;
            *(bf162*)(C1 + (size_t)rm * NSP + cn) =
                __floats2bfloat162_rn(acc1[ma][na][0], acc1[ma][na][1]);
            *(bf162*)(C1 + (size_t)(rm + 8) * NSP + cn) =
                __floats2bfloat162_rn(acc1[ma][na][2], acc1[ma][na][3]);
            *(bf162*)(C2 + (size_t)rm * NSP + cn) =
                __floats2bfloat162_rn(acc2[ma][na][0], acc2[ma][na][1]);
            *(bf162*)(C2 + (size_t)(rm + 8) * NSP + cn) =
                __floats2bfloat162_rn(acc2[ma][na][2], acc2[ma][na][3]);
        }
    }
}

// ---------------------------------------------------------------------------
// bsm: Mraw = Tg @ Tph^T (bf16 NT, split-K=8, atomics, pipelined) + row sums
// grid (4, 8, 4)
// ---------------------------------------------------------------------------
__global__ void __launch_bounds__(256) bsm() {
    const int ti = blockIdx.x >> 1, tj = blockIdx.x & 1;
    const int i0 = ti * 64, j0 = tj * 64;
    const int kb = blockIdx.y * 512;
    const int bz = blockIdx.z;
    const bf16* A = d_Tg + (size_t)bz * C_MID * NSP;
    const bf16* B = d_Tph + (size_t)bz * C_MID * NSP;

    __shared__ bf16 As[64 * 40], Bs[64 * 40];

    const int tid = threadIdx.x;
    const int lane = tid & 31, warp = tid >> 5;
    const int wm = warp >> 2, wn = warp & 3;
    const int gq = lane >> 2, tg = lane & 3;
    const int lr = tid >> 2, lc = (tid & 3) * 8;
    const int a_row = (lane & 7) + ((lane >> 3) & 1) * 8;
    const int a_col = (lane >> 4) * 8;
    const int b_nr = (lane & 7) + ((lane >> 4) & 1) * 8;
    const int b_kc = ((lane >> 3) & 1) * 8;

    float acc[2][2][4] = {};
    float sa = 0.f, sb = 0.f;
    const bool dosum = (ti == tj);

    uint4 va = *(const uint4*)(A + (size_t)(i0 + lr) * NSP + kb + lc);
    uint4 vv = *(const uint4*)(B + (size_t)(j0 + lr) * NSP + kb + lc);

    for (int k0 = 0; k0 < 512; k0 += 32) {
        if (dosum) { sa += sum8bf(va); sb += sum8bf(vv); }
        __syncthreads();
        *(uint4*)&As[lr * 40 + lc] = va;
        *(uint4*)&Bs[lr * 40 + lc] = vv;
        __syncthreads();
        if (k0 + 32 < 512) {
            va = *(const uint4*)(A + (size_t)(i0 + lr) * NSP + kb + k0 + 32 + lc);
            vv = *(const uint4*)(B + (size_t)(j0 + lr) * NSP + kb + k0 + 32 + lc);
        }
#pragma unroll
        for (int kk = 0; kk < 32; kk += 16) {
            uint32_t a[2][4], bbv[4];
#pragma unroll
            for (int ma = 0; ma < 2; ma++)
                ldsm4(a[ma], &As[(wm * 32 + ma * 16 + a_row) * 40 + kk + a_col]);
            ldsm4(bbv, &Bs[(wn * 16 + b_nr) * 40 + kk + b_kc]);
#pragma unroll
            for (int ma = 0; ma < 2; ma++) {
                mma_bf16(acc[ma][0], a[ma], bbv[0], bbv[1]);
                mma_bf16(acc[ma][1], a[ma], bbv[2], bbv[3]);
            }
        }
    }

    float* Mp = d_M + (size_t)bz * C_MID * C_MID;
#pragma unroll
    for (int ma = 0; ma < 2; ma++) {
        int rr = i0 + wm * 32 + ma * 16 + gq;
#pragma unroll
        for (int na = 0; na < 2; na++) {
            int cn = j0 + wn * 16 + na * 8 + 2 * tg;
            atomicAdd(&Mp[(size_t)rr * C_MID + cn],           acc[ma][na][0]);
            atomicAdd(&Mp[(size_t)rr * C_MID + cn + 1],       acc[ma][na][1]);
            atomicAdd(&Mp[(size_t)(rr + 8) * C_MID + cn],     acc[ma][na][2]);
            atomicAdd(&Mp[(size_t)(rr + 8) * C_MID + cn + 1], acc[ma][na][3]);
        }
    }
    if (dosum) {
        sa += __shfl_xor_sync(0xffffffffu, sa, 1);
        sa += __shfl_xor_sync(0xffffffffu, sa, 2);
        sb += __shfl_xor_sync(0xffffffffu, sb, 1);
        sb += __shfl_xor_sync(0xffffffffu, sb, 2);
        if ((tid & 3) == 0) {
            atomicAdd(&d_gs[bz * C_MID + i0 + lr], sa);
            atomicAdd(&d_ws[bz * C_MID + j0 + lr], sb);
        }
    }
}

// ---------------------------------------------------------------------------
// afold: Wm = out_w_slice @ Mfull (rank-1 fused), Afold = Wm@theta_w/N (bf16)
// grid (2, 4, 4)
// ---------------------------------------------------------------------------
__global__ void __launch_bounds__(256) afold(const float* __restrict__ out_w,
                                             const float* __restrict__ theta_w,
                                             const float* __restrict__ theta_b,
                                             const float* __restrict__ phi_b,
                                             const float* __restrict__ g_b,
                                             const float* __restrict__ out_b) {
    __shared__ float sm[11008];
    float* pbs = sm + 10560;
    float* wss = sm + 10688;
    float* tbs = sm + 10816;

    const int bz = blockIdx.z;
    const int i0 = blockIdx.y * 64;
    const int n0 = blockIdx.x * 128;
    const float* Mraw = d_M + (size_t)bz * C_MID * C_MID;

    const int tid = threadIdx.x;
    const int lane = tid & 31, warp = tid >> 5;
    const int wm = warp >> 2, wn = warp & 3;
    const int gq = lane >> 2, tg = lane & 3;
    const int alr = tid >> 3, alc = (tid & 7) * 4;
    const int blr = tid >> 3, bf4 = (tid & 7);

    if (tid < 128) {
        pbs[tid] = phi_b[tid];
        wss[tid] = d_ws[bz * C_MID + tid];
        tbs[tid] = theta_b[tid];
    }
    __syncthreads();

    float* As = sm;
    float* Bs = sm + 2304;
    float accW[2][4][4] = {};

    for (int k0 = 0; k0 < 128; k0 += 32) {
        float4 va0 = *(const float4*)(out_w + (size_t)(i0 + alr) * C_MID + k0 + alc);
        float4 va1 = *(const float4*)(out_w + (size_t)(i0 + alr + 32) * C_MID + k0 + alc);
        const int krow = k0 + blr;
        const float gsv = d_gs[bz * C_MID + krow];
        const float gbv = g_b[krow];
        float4 vb[4];
#pragma unroll
        for (int i = 0; i < 4; i++) {
            int c = (bf4 + 8 * i) * 4;
            float4 mr = *(const float4*)(Mraw + (size_t)krow * C_MID + c);
            float4 pb = *(const float4*)&pbs[c];
            float4 wv = *(const float4*)&wss[c];
            vb[i].x = mr.x + gsv * pb.x + gbv * (wv.x + 4096.f * pb.x);
            vb[i].y = mr.y + gsv * pb.y + gbv * (wv.y + 4096.f * pb.y);
            vb[i].z = mr.z + gsv * pb.z + gbv * (wv.z + 4096.f * pb.z);
            vb[i].w = mr.w + gsv * pb.w + gbv * (wv.w + 4096.f * pb.w);
        }
        __syncthreads();
        *(float4*)&As[alr * 36 + alc] = rtf4(va0);
        *(float4*)&As[(alr + 32) * 36 + alc] = rtf4(va1);
#pragma unroll
        for (int i = 0; i < 4; i++)
            *(float4*)&Bs[blr * 136 + (bf4 + 8 * i) * 4] = rtf4(vb[i]);
        __syncthreads();
#pragma unroll
        for (int kk = 0; kk < 32; kk += 8) {
            uint32_t a[2][4], b[4][2];
#pragma unroll
            for (int ma = 0; ma < 2; ma++) {
                int rb = wm * 32 + ma * 16 + gq;
                a[ma][0] = fbits(As[rb * 36 + kk + tg]);
                a[ma][1] = fbits(As[(rb + 8) * 36 + kk + tg]);
                a[ma][2] = fbits(As[rb * 36 + kk + 4 + tg]);
                a[ma][3] = fbits(As[(rb + 8) * 36 + kk + 4 + tg]);
            }
#pragma unroll
            for (int na = 0; na < 4; na++) {
                int cb = wn * 32 + na * 8 + gq;
                b[na][0] = fbits(Bs[(kk + tg) * 136 + cb]);
                b[na][1] = fbits(Bs[(kk + 4 + tg) * 136 + cb]);
            }
#pragma unroll
            for (int ma = 0; ma < 2; ma++)
#pragma unroll
                for (int na = 0; na < 4; na++)
                    mma_tf32(accW[ma][na], a[ma][0], a[ma][1], a[ma][2], a[ma][3],
                             b[na][0], b[na][1]);
        }
    }

    __syncthreads();
    float* Wm = sm;
#pragma unroll
    for (int ma = 0; ma < 2; ma++) {
        int rm = wm * 32 + ma * 16 + gq;
#pragma unroll
        for (int na = 0; na < 4; na++) {
            int cn = wn * 32 + na * 8 + 2 * tg;
            Wm[rm * 132 + cn]           = rtf(accW[ma][na][0]);
            Wm[rm * 132 + cn + 1]       = rtf(accW[ma][na][1]);
            Wm[(rm + 8) * 132 + cn]     = rtf(accW[ma][na][2]);
            Wm[(rm + 8) * 132 + cn + 1] = rtf(accW[ma][na][3]);
        }
    }

    float* Bs2 = sm + 8448;
    float accF[2][4][4] = {};
    const int trow = tid >> 4;
    const int tcol = (tid & 15) * 4;

    for (int k0 = 0; k0 < 128; k0 += 16) {
        float4 t0 = *(const float4*)(theta_w + (size_t)(k0 + trow) * C_IN + n0 + tcol);
        float4 t1 = *(const float4*)(theta_w + (size_t)(k0 + trow) * C_IN + n0 + tcol + 64);
        __syncthreads();
        *(float4*)&Bs2[trow * 132 + tcol] = rtf4(t0);
        *(float4*)&Bs2[trow * 132 + tcol + 64] = rtf4(t1);
        __syncthreads();
#pragma unroll
        for (int kk = 0; kk < 16; kk += 8) {
            uint32_t a[2][4], b[4][2];
#pragma unroll
            for (int ma = 0; ma < 2; ma++) {
                int rb = wm * 32 + ma * 16 + gq;
                a[ma][0] = fbits(Wm[rb * 132 + k0 + kk + tg]);
                a[ma][1] = fbits(Wm[(rb + 8) * 132 + k0 + kk + tg]);
                a[ma][2] = fbits(Wm[rb * 132 + k0 + kk + 4 + tg]);
                a[ma][3] = fbits(Wm[(rb + 8) * 132 + k0 + kk + 4 + tg]);
            }
#pragma unroll
            for (int na = 0; na < 4; na++) {
                int cb = wn * 32 + na * 8 + gq;
                b[na][0] = fbits(Bs2[(kk + tg) * 132 + cb]);
                b[na][1] = fbits(Bs2[(kk + 4 + tg) * 132 + cb]);
            }
#pragma unroll
            for (int ma = 0; ma < 2; ma++)
#pragma unroll
                for (int na = 0; na < 4; na++)
                    mma_tf32(accF[ma][na], a[ma][0], a[ma][1], a[ma][2], a[ma][3],
                             b[na][0], b[na][1]);
        }
    }

    bf16* Af = d_Af + (size_t)bz * C_IN * C_IN;
#pragma unroll
    for (int ma = 0; ma < 2; ma++) {
        int rm = i0 + wm * 32 + ma * 16 + gq;
#pragma unroll
        for (int na = 0; na < 4; na++) {
            int cn = n0 + wn * 32 + na * 8 + 2 * tg;
            *(bf162*)(Af + (size_t)rm * C_IN + cn) =
                __floats2bfloat162_rn(accF[ma][na][0] * INVN, accF[ma][na][1] * INVN);
            *(bf162*)(Af + (size_t)(rm + 8) * C_IN + cn) =
                __floats2bfloat162_rn(accF[ma][na][2] * INVN, accF[ma][na][3] * INVN);
        }
    }

    if (blockIdx.x == 0) {
        int r = warp * 8;
#pragma unroll
        for (int d = 0; d < 8; d++) {
            float cv = warp_dot128(Wm + (r + d) * 132, tbs) * INVN;
            if (lane == 0) d_cvec[bz * C_IN + i0 + r + d] = cv + out_b[i0 + r + d];
        }
    }
}

// ---------------------------------------------------------------------------
// final: out = Afold @ Xbf + X + cvec  (bf16 TC, reg-prefetch pipeline)
// grid (32, 4, 4)
// ---------------------------------------------------------------------------
__global__ void __launch_bounds__(256) final_k(const float* __restrict__ x,
                                               float* __restrict__ out) {
    __shared__ bf16 As[64 * 40], Bs[32 * 136];
    const int bz = blockIdx.z;
    const int m0 = blockIdx.y * 64;
    const int n0 = blockIdx.x * 128;
    const bf16* A = d_Af + (size_t)bz * C_IN * C_IN;
    const bf16* Xb16 = d_Xbf + (size_t)bz * C_IN * NSP;
    const float* Xb = x + (size_t)bz * C_IN * NSP;
    float* Ob = out + (size_t)bz * C_IN * NSP;

    const int tid = threadIdx.x;
    const int lane = tid & 31, warp = tid >> 5;
    const int wm = warp >> 2, wn = warp & 3;
    const int gq = lane >> 2, tg = lane & 3;
    const int lr = tid >> 2, lc = (tid & 3) * 8;       // A loader (64 rows x 32)
    const int br = tid >> 3, bc0 = (tid & 7) * 8;      // B loader (32 rows x 128)
    const int a_row = (lane & 7) + ((lane >> 3) & 1) * 8;
    const int a_col = (lane >> 4) * 8;
    const int bt_kr = (lane & 7) + ((lane >> 3) & 1) * 8;
    const int bt_nc = ((lane >> 4) & 1) * 8;

    float acc[2][4][4] = {};

    uint4 va = *(const uint4*)(A + (size_t)(m0 + lr) * C_IN + lc);
    uint4 xb0 = *(const uint4*)(Xb16 + (size_t)br * NSP + n0 + bc0);
    uint4 xb1 = *(const uint4*)(Xb16 + (size_t)br * NSP + n0 + bc0 + 64);

    for (int k0 = 0; k0 < 256; k0 += 32) {
        __syncthreads();
        *(uint4*)&As[lr * 40 + lc] = va;
        *(uint4*)&Bs[br * 136 + bc0] = xb0;
        *(uint4*)&Bs[br * 136 + bc0 + 64] = xb1;
        __syncthreads();
        if (k0 + 32 < 256) {
            int kn = k0 + 32;
            va = *(const uint4*)(A + (size_t)(m0 + lr) * C_IN + kn + lc);
            xb0 = *(const uint4*)(Xb16 + (size_t)(kn + br) * NSP + n0 + bc0);
            xb1 = *(const uint4*)(Xb16 + (size_t)(kn + br) * NSP + n0 + bc0 + 64);
        }
#pragma unroll
        for (int kk = 0; kk < 32; kk += 16) {
            uint32_t a[2][4], bb[2][4];
#pragma unroll
            for (int ma = 0; ma < 2; ma++)
                ldsm4(a[ma], &As[(wm * 32 + ma * 16 + a_row) * 40 + kk + a_col]);
#pragma unroll
            for (int pr = 0; pr < 2; pr++)
                ldsm4t(bb[pr], &Bs[(kk + bt_kr) * 136 + wn * 32 + pr * 16 + bt_nc]);
#pragma unroll
            for (int ma = 0; ma < 2; ma++)
#pragma unroll
                for (int na = 0; na < 4; na++)
                    mma_bf16(acc[ma][na], a[ma],
                             bb[na >> 1][(na & 1) * 2], bb[na >> 1][(na & 1) * 2 + 1]);
        }
    }

    const float* cb = d_cvec + bz * C_IN;
#pragma unroll
    for (int ma = 0; ma < 2; ma++) {
        int rm = m0 + wm * 32 + ma * 16 + gq;
        float c0 = cb[rm], c1 = cb[rm + 8];
#pragma unroll
        for (int na = 0; na < 4; na++) {
            int cn = n0 + wn * 32 + na * 8 + 2 * tg;
            float2 x0 = *(const float2*)(Xb + (size_t)rm * NSP + cn);
            float2 x1 = *(const float2*)(Xb + (size_t)(rm + 8) * NSP + cn);
            *(float2*)(Ob + (size_t)rm * NSP + cn) =
                make_float2(acc[ma][na][0] + x0.x + c0, acc[ma][na][1] + x0.y + c0);
            *(float2*)(Ob + (size_t)(rm + 8) * NSP + cn) =
                make_float2(acc[ma][na][2] + x1.x + c1, acc[ma][na][3] + x1.y + c1);
        }
    }
}

// ---------------------------------------------------------------------------
// Host launcher — 4 kernels
// ---------------------------------------------------------------------------
extern "C" void kernel_launch(void* const* d_in, const int* in_sizes, int n_in,
                              void* d_out, int out_size) {
    const float* x       = (const float*)d_in[0];
    const float* g_w     = (const float*)d_in[1];
    const float* g_b     = (const float*)d_in[2];
    const float* theta_w = (const float*)d_in[3];
    const float* theta_b = (const float*)d_in[4];
    const float* phi_w   = (const float*)d_in[5];
    const float* phi_b   = (const float*)d_in[6];
    const float* out_w   = (const float*)d_in[7];
    const float* out_b   = (const float*)d_in[8];
    float* out = (float*)d_out;

    proj<<<dim3(33, 2, 4), 256>>>(x, phi_w, g_w);
    bsm<<<dim3(4, 8, 4), 256>>>();
    afold<<<dim3(2, 4, 4), 256>>>(out_w, theta_w, theta_b, phi_b, g_b, out_b);
    final_k<<<dim3(32, 4, 4), 256>>>(x, out);
}

// round 9
// speedup vs baseline: 1.1238x; 1.1238x over previous
#include <cuda_runtime.h>
#include <cuda_bf16.h>
#include <cstdint>

#define BATCH 4
#define C_IN 256
#define C_MID 128
#define NSP 4096
#define INVN (1.0f/4096.0f)

typedef __nv_bfloat16 bf16;
typedef __nv_bfloat162 bf162;

// ---------------------------------------------------------------------------
// Device scratch
// ---------------------------------------------------------------------------
__device__ __align__(256) bf16  d_Xbf[BATCH * C_IN * NSP];   // X (bf16)
__device__ __align__(256) bf16  d_phw[C_MID * C_IN];         // phi_w (bf16)
__device__ __align__(256) bf16  d_gw [C_MID * C_IN];         // g_w (bf16)
__device__ __align__(256) bf16  d_Tph[BATCH * C_MID * NSP];
__device__ __align__(256) bf16  d_Tg [BATCH * C_MID * NSP];
__device__ __align__(256) float d_M  [BATCH * C_MID * C_MID];
__device__ __align__(256) float d_gs [BATCH * C_MID];
__device__ __align__(256) float d_ws [BATCH * C_MID];
__device__ __align__(256) bf16  d_Af [BATCH * C_IN * C_IN];
__device__ __align__(256) float d_cvec[BATCH * C_IN];

// ---------------------------------------------------------------------------
// Helpers
// ---------------------------------------------------------------------------
__device__ __forceinline__ void mma_bf16(float c[4], const uint32_t a[4],
                                         uint32_t b0, uint32_t b1) {
    asm volatile("mma.sync.aligned.m16n8k16.row.col.f32.bf16.bf16.f32 "
                 "{%0,%1,%2,%3}, {%4,%5,%6,%7}, {%8,%9}, {%0,%1,%2,%3};"
                 : "+f"(c[0]), "+f"(c[1]), "+f"(c[2]), "+f"(c[3])
                 : "r"(a[0]), "r"(a[1]), "r"(a[2]), "r"(a[3]), "r"(b0), "r"(b1));
}
__device__ __forceinline__ void mma_tf32(float c[4],
                                         uint32_t a0, uint32_t a1, uint32_t a2, uint32_t a3,
                                         uint32_t b0, uint32_t b1) {
    asm volatile("mma.sync.aligned.m16n8k8.row.col.f32.tf32.tf32.f32 "
                 "{%0,%1,%2,%3}, {%4,%5,%6,%7}, {%8,%9}, {%0,%1,%2,%3};"
                 : "+f"(c[0]), "+f"(c[1]), "+f"(c[2]), "+f"(c[3])
                 : "r"(a0), "r"(a1), "r"(a2), "r"(a3), "r"(b0), "r"(b1));
}
__device__ __forceinline__ void ldsm4(uint32_t r[4], const bf16* p) {
    uint32_t addr = (uint32_t)__cvta_generic_to_shared(p);
    asm volatile("ldmatrix.sync.aligned.m8n8.x4.shared.b16 {%0,%1,%2,%3}, [%4];"
                 : "=r"(r[0]), "=r"(r[1]), "=r"(r[2]), "=r"(r[3]) : "r"(addr));
}
__device__ __forceinline__ void ldsm4t(uint32_t r[4], const bf16* p) {
    uint32_t addr = (uint32_t)__cvta_generic_to_shared(p);
    asm volatile("ldmatrix.sync.aligned.m8n8.x4.trans.shared.b16 {%0,%1,%2,%3}, [%4];"
                 : "=r"(r[0]), "=r"(r[1]), "=r"(r[2]), "=r"(r[3]) : "r"(addr));
}
__device__ __forceinline__ void cp16(bf16* s, const bf16* g) {
    uint32_t sa = (uint32_t)__cvta_generic_to_shared(s);
    asm volatile("cp.async.cg.shared.global [%0], [%1], 16;" :: "r"(sa), "l"(g));
}
#define CP_COMMIT() asm volatile("cp.async.commit_group;" ::: "memory")
#define CP_WAIT1()  asm volatile("cp.async.wait_group 1;" ::: "memory")

__device__ __forceinline__ uint32_t fbits(float f) { return __float_as_uint(f); }
__device__ __forceinline__ float rtf(float f) {
    uint32_t u;
    asm("cvt.rna.tf32.f32 %0, %1;" : "=r"(u) : "f"(f));
    return __uint_as_float(u);
}
__device__ __forceinline__ float4 rtf4(float4 v) {
    return make_float4(rtf(v.x), rtf(v.y), rtf(v.z), rtf(v.w));
}
__device__ __forceinline__ uint2 f4_to_bf(float4 v) {
    bf162 lo = __floats2bfloat162_rn(v.x, v.y);
    bf162 hi = __floats2bfloat162_rn(v.z, v.w);
    uint2 r;
    r.x = *(uint32_t*)&lo;
    r.y = *(uint32_t*)&hi;
    return r;
}
__device__ __forceinline__ float sum8bf(uint4 v) {
    const bf162* p = (const bf162*)&v;
    float s = 0.f;
#pragma unroll
    for (int i = 0; i < 4; i++) {
        float2 f = __bfloat1622float2(p[i]);
        s += f.x + f.y;
    }
    return s;
}
__device__ __forceinline__ float warp_dot128(const float* __restrict__ row,
                                             const float* __restrict__ v) {
    int lane = threadIdx.x & 31;
    float4 r0 = *(const float4*)(row + lane * 4);
    float4 v0 = *(const float4*)(v + lane * 4);
    float a = r0.x * v0.x + r0.y * v0.y + r0.z * v0.z + r0.w * v0.w;
#pragma unroll
    for (int o = 16; o; o >>= 1) a += __shfl_xor_sync(0xffffffffu, a, o);
    return a;
}

// ---------------------------------------------------------------------------
// convert_init: x->bf16, phi_w->bf16, g_w->bf16, zero M/gs/ws. grid 281
// ---------------------------------------------------------------------------
__global__ void __launch_bounds__(256) convert_init(const float* __restrict__ x,
                                                    const float* __restrict__ phi_w,
                                                    const float* __restrict__ g_w) {
    const int b = blockIdx.x, tid = threadIdx.x;
    if (b < 256) {
        const float4* src = (const float4*)x + (size_t)b * 4096;
        uint2* dst = (uint2*)d_Xbf + (size_t)b * 4096;
#pragma unroll 4
        for (int i = tid; i < 4096; i += 256) dst[i] = f4_to_bf(src[i]);
    } else if (b < 264) {
        const float4* src = (const float4*)phi_w + (b - 256) * 1024;
        uint2* dst = (uint2*)d_phw + (b - 256) * 1024;
#pragma unroll
        for (int i = tid; i < 1024; i += 256) dst[i] = f4_to_bf(src[i]);
    } else if (b < 272) {
        const float4* src = (const float4*)g_w + (b - 264) * 1024;
        uint2* dst = (uint2*)d_gw + (b - 264) * 1024;
#pragma unroll
        for (int i = tid; i < 1024; i += 256) dst[i] = f4_to_bf(src[i]);
    } else if (b < 280) {
        float4* M4 = (float4*)d_M + (b - 272) * 2048;
        float4 z4 = make_float4(0, 0, 0, 0);
#pragma unroll
        for (int i = tid; i < 2048; i += 256) M4[i] = z4;
    } else {
        float4 z4 = make_float4(0, 0, 0, 0);
        if (tid < 128) {
            ((float4*)d_gs)[tid] = z4;
            ((float4*)d_ws)[tid] = z4;
        }
    }
}

// ---------------------------------------------------------------------------
// proj: Tph = phw @ Xbf, Tg = gw @ Xbf (bf16, cp.async 3-stage)
// grid (32, 2, 4)
// ---------------------------------------------------------------------------
__global__ void __launch_bounds__(256) proj() {
    __shared__ bf16 As1[3][64 * 40], As2[3][64 * 40], Bs[3][32 * 136];
    const int bz = blockIdx.z;
    const int m0 = blockIdx.y * 64;
    const int n0 = blockIdx.x * 128;
    const bf16* Xbf = d_Xbf + (size_t)bz * C_IN * NSP;

    const int tid = threadIdx.x;
    const int lane = tid & 31, warp = tid >> 5;
    const int wm = warp >> 2, wn = warp & 3;
    const int gq = lane >> 2, tg = lane & 3;
    const int ar = tid >> 2, ac = (tid & 3) * 8;     // A tile 64x32 = 256 chunks
    const int br = tid >> 3, bc = (tid & 7) * 8;     // B tile 32x128 = 512 chunks
    const int a_row = (lane & 7) + ((lane >> 3) & 1) * 8;
    const int a_col = (lane >> 4) * 8;
    const int bt_kr = (lane & 7) + ((lane >> 3) & 1) * 8;
    const int bt_nc = ((lane >> 4) & 1) * 8;

    float acc1[2][4][4] = {}, acc2[2][4][4] = {};

    auto issue = [&](int k0, int st) {
        cp16(&As1[st][ar * 40 + ac], d_phw + (size_t)(m0 + ar) * 256 + k0 + ac);
        cp16(&As2[st][ar * 40 + ac], d_gw + (size_t)(m0 + ar) * 256 + k0 + ac);
        cp16(&Bs[st][br * 136 + bc], Xbf + (size_t)(k0 + br) * NSP + n0 + bc);
        cp16(&Bs[st][br * 136 + bc + 64], Xbf + (size_t)(k0 + br) * NSP + n0 + bc + 64);
    };

    issue(0, 0); CP_COMMIT();
    issue(32, 1); CP_COMMIT();

    for (int i = 0; i < 8; i++) {
        CP_WAIT1();
        __syncthreads();
        int kn = (i + 2) * 32;
        if (kn < 256) issue(kn, (i + 2) % 3);
        CP_COMMIT();
        const int st = i % 3;
#pragma unroll
        for (int kk = 0; kk < 32; kk += 16) {
            uint32_t a1[2][4], a2[2][4], bb[2][4];
#pragma unroll
            for (int ma = 0; ma < 2; ma++) {
                int rb = wm * 32 + ma * 16;
                ldsm4(a1[ma], &As1[st][(rb + a_row) * 40 + kk + a_col]);
                ldsm4(a2[ma], &As2[st][(rb + a_row) * 40 + kk + a_col]);
            }
#pragma unroll
            for (int pr = 0; pr < 2; pr++)
                ldsm4t(bb[pr], &Bs[st][(kk + bt_kr) * 136 + wn * 32 + pr * 16 + bt_nc]);
#pragma unroll
            for (int ma = 0; ma < 2; ma++)
#pragma unroll
                for (int na = 0; na < 4; na++) {
                    uint32_t b0 = bb[na >> 1][(na & 1) * 2];
                    uint32_t b1 = bb[na >> 1][(na & 1) * 2 + 1];
                    mma_bf16(acc1[ma][na], a1[ma], b0, b1);
                    mma_bf16(acc2[ma][na], a2[ma], b0, b1);
                }
        }
    }

    bf16* C1 = d_Tph + (size_t)bz * C_MID * NSP;
    bf16* C2 = d_Tg + (size_t)bz * C_MID * NSP;
#pragma unroll
    for (int ma = 0; ma < 2; ma++) {
        int rm = m0 + wm * 32 + ma * 16 + gq;
#pragma unroll
        for (int na = 0; na < 4; na++) {
            int cn = n0 + wn * 32 + na * 8 + 2 * tg;
            *(bf162*)(C1 + (size_t)rm * NSP + cn) =
                __floats2bfloat162_rn(acc1[ma][na][0], acc1[ma][na][1]);
            *(bf162*)(C1 + (size_t)(rm + 8) * NSP + cn) =
                __floats2bfloat162_rn(acc1[ma][na][2], acc1[ma][na][3]);
            *(bf162*)(C2 + (size_t)rm * NSP + cn) =
                __floats2bfloat162_rn(acc2[ma][na][0], acc2[ma][na][1]);
            *(bf162*)(C2 + (size_t)(rm + 8) * NSP + cn) =
                __floats2bfloat162_rn(acc2[ma][na][2], acc2[ma][na][3]);
        }
    }
}

// ---------------------------------------------------------------------------
// bsm: Mraw = Tg @ Tph^T (NT bf16, split-K=8, cp.async 3-stage) + row sums
// grid (4, 8, 4)
// ---------------------------------------------------------------------------
__global__ void __launch_bounds__(256) bsm() {
    __shared__ bf16 As[3][64 * 40], Bs[3][64 * 40];
    const int ti = blockIdx.x >> 1, tj = blockIdx.x & 1;
    const int i0 = ti * 64, j0 = tj * 64;
    const int kb = blockIdx.y * 512;
    const int bz = blockIdx.z;
    const bf16* A = d_Tg + (size_t)bz * C_MID * NSP;
    const bf16* B = d_Tph + (size_t)bz * C_MID * NSP;

    const int tid = threadIdx.x;
    const int lane = tid & 31, warp = tid >> 5;
    const int wm = warp >> 2, wn = warp & 3;
    const int gq = lane >> 2, tg = lane & 3;
    const int lr = tid >> 2, lc = (tid & 3) * 8;
    const int a_row = (lane & 7) + ((lane >> 3) & 1) * 8;
    const int a_col = (lane >> 4) * 8;
    const int b_nr = (lane & 7) + ((lane >> 4) & 1) * 8;
    const int b_kc = ((lane >> 3) & 1) * 8;

    float acc[2][2][4] = {};
    float sa = 0.f, sb = 0.f;
    const bool dosum = (ti == tj);

    auto issue = [&](int k0, int st) {
        cp16(&As[st][lr * 40 + lc], A + (size_t)(i0 + lr) * NSP + kb + k0 + lc);
        cp16(&Bs[st][lr * 40 + lc], B + (size_t)(j0 + lr) * NSP + kb + k0 + lc);
    };

    issue(0, 0); CP_COMMIT();
    issue(32, 1); CP_COMMIT();

    for (int i = 0; i < 16; i++) {
        CP_WAIT1();
        __syncthreads();
        int kn = (i + 2) * 32;
        if (kn < 512) issue(kn, (i + 2) % 3);
        CP_COMMIT();
        const int st = i % 3;
        if (dosum) {
            sa += sum8bf(*(const uint4*)&As[st][lr * 40 + lc]);
            sb += sum8bf(*(const uint4*)&Bs[st][lr * 40 + lc]);
        }
#pragma unroll
        for (int kk = 0; kk < 32; kk += 16) {
            uint32_t a[2][4], bbv[4];
#pragma unroll
            for (int ma = 0; ma < 2; ma++)
                ldsm4(a[ma], &As[st][(wm * 32 + ma * 16 + a_row) * 40 + kk + a_col]);
            ldsm4(bbv, &Bs[st][(wn * 16 + b_nr) * 40 + kk + b_kc]);
#pragma unroll
            for (int ma = 0; ma < 2; ma++) {
                mma_bf16(acc[ma][0], a[ma], bbv[0], bbv[1]);
                mma_bf16(acc[ma][1], a[ma], bbv[2], bbv[3]);
            }
        }
    }

    float* Mp = d_M + (size_t)bz * C_MID * C_MID;
#pragma unroll
    for (int ma = 0; ma < 2; ma++) {
        int rr = i0 + wm * 32 + ma * 16 + gq;
#pragma unroll
        for (int na = 0; na < 2; na++) {
            int cn = j0 + wn * 16 + na * 8 + 2 * tg;
            atomicAdd(&Mp[(size_t)rr * C_MID + cn],           acc[ma][na][0]);
            atomicAdd(&Mp[(size_t)rr * C_MID + cn + 1],       acc[ma][na][1]);
            atomicAdd(&Mp[(size_t)(rr + 8) * C_MID + cn],     acc[ma][na][2]);
            atomicAdd(&Mp[(size_t)(rr + 8) * C_MID + cn + 1], acc[ma][na][3]);
        }
    }
    if (dosum) {
        sa += __shfl_xor_sync(0xffffffffu, sa, 1);
        sa += __shfl_xor_sync(0xffffffffu, sa, 2);
        sb += __shfl_xor_sync(0xffffffffu, sb, 1);
        sb += __shfl_xor_sync(0xffffffffu, sb, 2);
        if ((tid & 3) == 0) {
            atomicAdd(&d_gs[bz * C_MID + i0 + lr], sa);
            atomicAdd(&d_ws[bz * C_MID + j0 + lr], sb);
        }
    }
}

// ---------------------------------------------------------------------------
// afold: Wm = out_w_slice @ Mfull (rank-1 fused), Afold = Wm@theta_w/N (bf16)
// grid (2, 4, 4)
// ---------------------------------------------------------------------------
__global__ void __launch_bounds__(256) afold(const float* __restrict__ out_w,
                                             const float* __restrict__ theta_w,
                                             const float* __restrict__ theta_b,
                                             const float* __restrict__ phi_b,
                                             const float* __restrict__ g_b,
                                             const float* __restrict__ out_b) {
    __shared__ float sm[11008];
    float* pbs = sm + 10560;
    float* wss = sm + 10688;
    float* tbs = sm + 10816;

    const int bz = blockIdx.z;
    const int i0 = blockIdx.y * 64;
    const int n0 = blockIdx.x * 128;
    const float* Mraw = d_M + (size_t)bz * C_MID * C_MID;

    const int tid = threadIdx.x;
    const int lane = tid & 31, warp = tid >> 5;
    const int wm = warp >> 2, wn = warp & 3;
    const int gq = lane >> 2, tg = lane & 3;
    const int alr = tid >> 3, alc = (tid & 7) * 4;
    const int blr = tid >> 3, bf4 = (tid & 7);

    if (tid < 128) {
        pbs[tid] = phi_b[tid];
        wss[tid] = d_ws[bz * C_MID + tid];
        tbs[tid] = theta_b[tid];
    }
    __syncthreads();

    float* As = sm;
    float* Bs = sm + 2304;
    float accW[2][4][4] = {};

    for (int k0 = 0; k0 < 128; k0 += 32) {
        float4 va0 = *(const float4*)(out_w + (size_t)(i0 + alr) * C_MID + k0 + alc);
        float4 va1 = *(const float4*)(out_w + (size_t)(i0 + alr + 32) * C_MID + k0 + alc);
        const int krow = k0 + blr;
        const float gsv = d_gs[bz * C_MID + krow];
        const float gbv = g_b[krow];
        float4 vb[4];
#pragma unroll
        for (int i = 0; i < 4; i++) {
            int c = (bf4 + 8 * i) * 4;
            float4 mr = *(const float4*)(Mraw + (size_t)krow * C_MID + c);
            float4 pb = *(const float4*)&pbs[c];
            float4 wv = *(const float4*)&wss[c];
            vb[i].x = mr.x + gsv * pb.x + gbv * (wv.x + 4096.f * pb.x);
            vb[i].y = mr.y + gsv * pb.y + gbv * (wv.y + 4096.f * pb.y);
            vb[i].z = mr.z + gsv * pb.z + gbv * (wv.z + 4096.f * pb.z);
            vb[i].w = mr.w + gsv * pb.w + gbv * (wv.w + 4096.f * pb.w);
        }
        __syncthreads();
        *(float4*)&As[alr * 36 + alc] = rtf4(va0);
        *(float4*)&As[(alr + 32) * 36 + alc] = rtf4(va1);
#pragma unroll
        for (int i = 0; i < 4; i++)
            *(float4*)&Bs[blr * 136 + (bf4 + 8 * i) * 4] = rtf4(vb[i]);
        __syncthreads();
#pragma unroll
        for (int kk = 0; kk < 32; kk += 8) {
            uint32_t a[2][4], b[4][2];
#pragma unroll
            for (int ma = 0; ma < 2; ma++) {
                int rb = wm * 32 + ma * 16 + gq;
                a[ma][0] = fbits(As[rb * 36 + kk + tg]);
                a[ma][1] = fbits(As[(rb + 8) * 36 + kk + tg]);
                a[ma][2] = fbits(As[rb * 36 + kk + 4 + tg]);
                a[ma][3] = fbits(As[(rb + 8) * 36 + kk + 4 + tg]);
            }
#pragma unroll
            for (int na = 0; na < 4; na++) {
                int cb = wn * 32 + na * 8 + gq;
                b[na][0] = fbits(Bs[(kk + tg) * 136 + cb]);
                b[na][1] = fbits(Bs[(kk + 4 + tg) * 136 + cb]);
            }
#pragma unroll
            for (int ma = 0; ma < 2; ma++)
#pragma unroll
                for (int na = 0; na < 4; na++)
                    mma_tf32(accW[ma][na], a[ma][0], a[ma][1], a[ma][2], a[ma][3],
                             b[na][0], b[na][1]);
        }
    }

    __syncthreads();
    float* Wm = sm;
#pragma unroll
    for (int ma = 0; ma < 2; ma++) {
        int rm = wm * 32 + ma * 16 + gq;
#pragma unroll
        for (int na = 0; na < 4; na++) {
            int cn = wn * 32 + na * 8 + 2 * tg;
            Wm[rm * 132 + cn]           = rtf(accW[ma][na][0]);
            Wm[rm * 132 + cn + 1]       = rtf(accW[ma][na][1]);
            Wm[(rm + 8) * 132 + cn]     = rtf(accW[ma][na][2]);
            Wm[(rm + 8) * 132 + cn + 1] = rtf(accW[ma][na][3]);
        }
    }

    float* Bs2 = sm + 8448;
    float accF[2][4][4] = {};
    const int trow = tid >> 4;
    const int tcol = (tid & 15) * 4;

    for (int k0 = 0; k0 < 128; k0 += 16) {
        float4 t0 = *(const float4*)(theta_w + (size_t)(k0 + trow) * C_IN + n0 + tcol);
        float4 t1 = *(const float4*)(theta_w + (size_t)(k0 + trow) * C_IN + n0 + tcol + 64);
        __syncthreads();
        *(float4*)&Bs2[trow * 132 + tcol] = rtf4(t0);
        *(float4*)&Bs2[trow * 132 + tcol + 64] = rtf4(t1);
        __syncthreads();
#pragma unroll
        for (int kk = 0; kk < 16; kk += 8) {
            uint32_t a[2][4], b[4][2];
#pragma unroll
            for (int ma = 0; ma < 2; ma++) {
                int rb = wm * 32 + ma * 16 + gq;
                a[ma][0] = fbits(Wm[rb * 132 + k0 + kk + tg]);
                a[ma][1] = fbits(Wm[(rb + 8) * 132 + k0 + kk + tg]);
                a[ma][2] = fbits(Wm[rb * 132 + k0 + kk + 4 + tg]);
                a[ma][3] = fbits(Wm[(rb + 8) * 132 + k0 + kk + 4 + tg]);
            }
#pragma unroll
            for (int na = 0; na < 4; na++) {
                int cb = wn * 32 + na * 8 + gq;
                b[na][0] = fbits(Bs2[(kk + tg) * 132 + cb]);
                b[na][1] = fbits(Bs2[(kk + 4 + tg) * 132 + cb]);
            }
#pragma unroll
            for (int ma = 0; ma < 2; ma++)
#pragma unroll
                for (int na = 0; na < 4; na++)
                    mma_tf32(accF[ma][na], a[ma][0], a[ma][1], a[ma][2], a[ma][3],
                             b[na][0], b[na][1]);
        }
    }

    bf16* Af = d_Af + (size_t)bz * C_IN * C_IN;
#pragma unroll
    for (int ma = 0; ma < 2; ma++) {
        int rm = i0 + wm * 32 + ma * 16 + gq;
#pragma unroll
        for (int na = 0; na < 4; na++) {
            int cn = n0 + wn * 32 + na * 8 + 2 * tg;
            *(bf162*)(Af + (size_t)rm * C_IN + cn) =
                __floats2bfloat162_rn(accF[ma][na][0] * INVN, accF[ma][na][1] * INVN);
            *(bf162*)(Af + (size_t)(rm + 8) * C_IN + cn) =
                __floats2bfloat162_rn(accF[ma][na][2] * INVN, accF[ma][na][3] * INVN);
        }
    }

    if (blockIdx.x == 0) {
        int r = warp * 8;
#pragma unroll
        for (int d = 0; d < 8; d++) {
            float cv = warp_dot128(Wm + (r + d) * 132, tbs) * INVN;
            if (lane == 0) d_cvec[bz * C_IN + i0 + r + d] = cv + out_b[i0 + r + d];
        }
    }
}

// ---------------------------------------------------------------------------
// final: out = Afold @ Xbf + X + cvec  (bf16, cp.async 3-stage)
// grid (32, 4, 4)
// ---------------------------------------------------------------------------
__global__ void __launch_bounds__(256) final_k(const float* __restrict__ x,
                                               float* __restrict__ out) {
    __shared__ bf16 As[3][64 * 40], Bs[3][32 * 136];
    const int bz = blockIdx.z;
    const int m0 = blockIdx.y * 64;
    const int n0 = blockIdx.x * 128;
    const bf16* A = d_Af + (size_t)bz * C_IN * C_IN;
    const bf16* Xb16 = d_Xbf + (size_t)bz * C_IN * NSP;
    const float* Xb = x + (size_t)bz * C_IN * NSP;
    float* Ob = out + (size_t)bz * C_IN * NSP;

    const int tid = threadIdx.x;
    const int lane = tid & 31, warp = tid >> 5;
    const int wm = warp >> 2, wn = warp & 3;
    const int gq = lane >> 2, tg = lane & 3;
    const int ar = tid >> 2, ac = (tid & 3) * 8;
    const int br = tid >> 3, bc = (tid & 7) * 8;
    const int a_row = (lane & 7) + ((lane >> 3) & 1) * 8;
    const int a_col = (lane >> 4) * 8;
    const int bt_kr = (lane & 7) + ((lane >> 3) & 1) * 8;
    const int bt_nc = ((lane >> 4) & 1) * 8;

    float acc[2][4][4] = {};

    auto issue = [&](int k0, int st) {
        cp16(&As[st][ar * 40 + ac], A + (size_t)(m0 + ar) * C_IN + k0 + ac);
        cp16(&Bs[st][br * 136 + bc], Xb16 + (size_t)(k0 + br) * NSP + n0 + bc);
        cp16(&Bs[st][br * 136 + bc + 64], Xb16 + (size_t)(k0 + br) * NSP + n0 + bc + 64);
    };

    issue(0, 0); CP_COMMIT();
    issue(32, 1); CP_COMMIT();

    for (int i = 0; i < 8; i++) {
        CP_WAIT1();
        __syncthreads();
        int kn = (i + 2) * 32;
        if (kn < 256) issue(kn, (i + 2) % 3);
        CP_COMMIT();
        const int st = i % 3;
#pragma unroll
        for (int kk = 0; kk < 32; kk += 16) {
            uint32_t a[2][4], bb[2][4];
#pragma unroll
            for (int ma = 0; ma < 2; ma++)
                ldsm4(a[ma], &As[st][(wm * 32 + ma * 16 + a_row) * 40 + kk + a_col]);
#pragma unroll
            for (int pr = 0; pr < 2; pr++)
                ldsm4t(bb[pr], &Bs[st][(kk + bt_kr) * 136 + wn * 32 + pr * 16 + bt_nc]);
#pragma unroll
            for (int ma = 0; ma < 2; ma++)
#pragma unroll
                for (int na = 0; na < 4; na++)
                    mma_bf16(acc[ma][na], a[ma],
                             bb[na >> 1][(na & 1) * 2], bb[na >> 1][(na & 1) * 2 + 1]);
        }
    }

    const float* cb = d_cvec + bz * C_IN;
#pragma unroll
    for (int ma = 0; ma < 2; ma++) {
        int rm = m0 + wm * 32 + ma * 16 + gq;
        float c0 = cb[rm], c1 = cb[rm + 8];
#pragma unroll
        for (int na = 0; na < 4; na++) {
            int cn = n0 + wn * 32 + na * 8 + 2 * tg;
            float2 x0 = *(const float2*)(Xb + (size_t)rm * NSP + cn);
            float2 x1 = *(const float2*)(Xb + (size_t)(rm + 8) * NSP + cn);
            *(float2*)(Ob + (size_t)rm * NSP + cn) =
                make_float2(acc[ma][na][0] + x0.x + c0, acc[ma][na][1] + x0.y + c0);
            *(float2*)(Ob + (size_t)(rm + 8) * NSP + cn) =
                make_float2(acc[ma][na][2] + x1.x + c1, acc[ma][na][3] + x1.y + c1);
        }
    }
}

// ---------------------------------------------------------------------------
// Host launcher — 5 kernels
// ---------------------------------------------------------------------------
extern "C" void kernel_launch(void* const* d_in, const int* in_sizes, int n_in,
                              void* d_out, int out_size) {
    const float* x       = (const float*)d_in[0];
    const float* g_w     = (const float*)d_in[1];
    const float* g_b     = (const float*)d_in[2];
    const float* theta_w = (const float*)d_in[3];
    const float* theta_b = (const float*)d_in[4];
    const float* phi_w   = (const float*)d_in[5];
    const float* phi_b   = (const float*)d_in[6];
    const float* out_w   = (const float*)d_in[7];
    const float* out_b   = (const float*)d_in[8];
    float* out = (float*)d_out;

    convert_init<<<281, 256>>>(x, phi_w, g_w);
    proj<<<dim3(32, 2, 4), 256>>>();
    bsm<<<dim3(4, 8, 4), 256>>>();
    afold<<<dim3(2, 4, 4), 256>>>(out_w, theta_w, theta_b, phi_b, g_b, out_b);
    final_k<<<dim3(32, 4, 4), 256>>>(x, out);
}

// round 10
// speedup vs baseline: 1.2755x; 1.1349x over previous
#include <cuda_runtime.h>
#include <cuda_bf16.h>
#include <cstdint>

#define BATCH 4
#define C_IN 256
#define C_MID 128
#define NSP 4096
#define INVN (1.0f/4096.0f)

typedef __nv_bfloat16 bf16;
typedef __nv_bfloat162 bf162;

// ---------------------------------------------------------------------------
// Device scratch
// ---------------------------------------------------------------------------
__device__ __align__(256) bf16  d_Xbf[BATCH * C_IN * NSP];   // X (bf16)
__device__ __align__(256) bf16  d_phw[C_MID * C_IN];         // phi_w (bf16)
__device__ __align__(256) bf16  d_gw [C_MID * C_IN];         // g_w (bf16)
__device__ __align__(256) bf16  d_thw[C_MID * C_IN];         // theta_w (bf16)
__device__ __align__(256) bf16  d_ow [C_IN * C_MID];         // out_w (bf16)
__device__ __align__(256) bf16  d_Tph[BATCH * C_MID * NSP];
__device__ __align__(256) bf16  d_Tg [BATCH * C_MID * NSP];
__device__ __align__(256) float d_M  [BATCH * C_MID * C_MID];
__device__ __align__(256) float d_gs [BATCH * C_MID];
__device__ __align__(256) float d_ws [BATCH * C_MID];
__device__ __align__(256) float d_W  [BATCH * C_IN * C_MID]; // Wfull fp32
__device__ __align__(256) bf16  d_Af [BATCH * C_IN * C_IN];
__device__ __align__(256) float d_cvec[BATCH * C_IN];

// ---------------------------------------------------------------------------
// Helpers
// ---------------------------------------------------------------------------
__device__ __forceinline__ void mma_bf16(float c[4], const uint32_t a[4],
                                         uint32_t b0, uint32_t b1) {
    asm volatile("mma.sync.aligned.m16n8k16.row.col.f32.bf16.bf16.f32 "
                 "{%0,%1,%2,%3}, {%4,%5,%6,%7}, {%8,%9}, {%0,%1,%2,%3};"
                 : "+f"(c[0]), "+f"(c[1]), "+f"(c[2]), "+f"(c[3])
                 : "r"(a[0]), "r"(a[1]), "r"(a[2]), "r"(a[3]), "r"(b0), "r"(b1));
}
__device__ __forceinline__ void ldsm4(uint32_t r[4], const bf16* p) {
    uint32_t addr = (uint32_t)__cvta_generic_to_shared(p);
    asm volatile("ldmatrix.sync.aligned.m8n8.x4.shared.b16 {%0,%1,%2,%3}, [%4];"
                 : "=r"(r[0]), "=r"(r[1]), "=r"(r[2]), "=r"(r[3]) : "r"(addr));
}
__device__ __forceinline__ void ldsm4t(uint32_t r[4], const bf16* p) {
    uint32_t addr = (uint32_t)__cvta_generic_to_shared(p);
    asm volatile("ldmatrix.sync.aligned.m8n8.x4.trans.shared.b16 {%0,%1,%2,%3}, [%4];"
                 : "=r"(r[0]), "=r"(r[1]), "=r"(r[2]), "=r"(r[3]) : "r"(addr));
}
__device__ __forceinline__ void cp16(bf16* s, const bf16* g) {
    uint32_t sa = (uint32_t)__cvta_generic_to_shared(s);
    asm volatile("cp.async.cg.shared.global [%0], [%1], 16;" :: "r"(sa), "l"(g));
}
#define CP_COMMIT() asm volatile("cp.async.commit_group;" ::: "memory")
#define CP_WAIT1()  asm volatile("cp.async.wait_group 1;" ::: "memory")

__device__ __forceinline__ uint2 f4_to_bf(float4 v) {
    bf162 lo = __floats2bfloat162_rn(v.x, v.y);
    bf162 hi = __floats2bfloat162_rn(v.z, v.w);
    uint2 r;
    r.x = *(uint32_t*)&lo;
    r.y = *(uint32_t*)&hi;
    return r;
}
__device__ __forceinline__ float sum8bf(uint4 v) {
    const bf162* p = (const bf162*)&v;
    float s = 0.f;
#pragma unroll
    for (int i = 0; i < 4; i++) {
        float2 f = __bfloat1622float2(p[i]);
        s += f.x + f.y;
    }
    return s;
}

// ---------------------------------------------------------------------------
// convert_init: x/phi_w/g_w/theta_w/out_w -> bf16, zero M/gs/ws. grid 297
// ---------------------------------------------------------------------------
__global__ void __launch_bounds__(256) convert_init(const float* __restrict__ x,
                                                    const float* __restrict__ phi_w,
                                                    const float* __restrict__ g_w,
                                                    const float* __restrict__ theta_w,
                                                    const float* __restrict__ out_w) {
    const int b = blockIdx.x, tid = threadIdx.x;
    if (b < 256) {
        const float4* src = (const float4*)x + (size_t)b * 4096;
        uint2* dst = (uint2*)d_Xbf + (size_t)b * 4096;
#pragma unroll 4
        for (int i = tid; i < 4096; i += 256) dst[i] = f4_to_bf(src[i]);
    } else if (b < 264) {
        const float4* src = (const float4*)phi_w + (b - 256) * 1024;
        uint2* dst = (uint2*)d_phw + (b - 256) * 1024;
#pragma unroll
        for (int i = tid; i < 1024; i += 256) dst[i] = f4_to_bf(src[i]);
    } else if (b < 272) {
        const float4* src = (const float4*)g_w + (b - 264) * 1024;
        uint2* dst = (uint2*)d_gw + (b - 264) * 1024;
#pragma unroll
        for (int i = tid; i < 1024; i += 256) dst[i] = f4_to_bf(src[i]);
    } else if (b < 280) {
        const float4* src = (const float4*)theta_w + (b - 272) * 1024;
        uint2* dst = (uint2*)d_thw + (b - 272) * 1024;
#pragma unroll
        for (int i = tid; i < 1024; i += 256) dst[i] = f4_to_bf(src[i]);
    } else if (b < 288) {
        const float4* src = (const float4*)out_w + (b - 280) * 1024;
        uint2* dst = (uint2*)d_ow + (b - 280) * 1024;
#pragma unroll
        for (int i = tid; i < 1024; i += 256) dst[i] = f4_to_bf(src[i]);
    } else if (b < 296) {
        float4* M4 = (float4*)d_M + (b - 288) * 2048;
        float4 z4 = make_float4(0, 0, 0, 0);
#pragma unroll
        for (int i = tid; i < 2048; i += 256) M4[i] = z4;
    } else {
        float4 z4 = make_float4(0, 0, 0, 0);
        if (tid < 128) {
            ((float4*)d_gs)[tid] = z4;
            ((float4*)d_ws)[tid] = z4;
        }
    }
}

// ---------------------------------------------------------------------------
// proj: Tph = phw @ Xbf, Tg = gw @ Xbf (bf16, cp.async 3-stage). grid (32,2,4)
// ---------------------------------------------------------------------------
__global__ void __launch_bounds__(256) proj() {
    __shared__ bf16 As1[3][64 * 40], As2[3][64 * 40], Bs[3][32 * 136];
    const int bz = blockIdx.z;
    const int m0 = blockIdx.y * 64;
    const int n0 = blockIdx.x * 128;
    const bf16* Xbf = d_Xbf + (size_t)bz * C_IN * NSP;

    const int tid = threadIdx.x;
    const int lane = tid & 31, warp = tid >> 5;
    const int wm = warp >> 2, wn = warp & 3;
    const int gq = lane >> 2, tg = lane & 3;
    const int ar = tid >> 2, ac = (tid & 3) * 8;
    const int br = tid >> 3, bc = (tid & 7) * 8;
    const int a_row = (lane & 7) + ((lane >> 3) & 1) * 8;
    const int a_col = (lane >> 4) * 8;
    const int bt_kr = (lane & 7) + ((lane >> 3) & 1) * 8;
    const int bt_nc = ((lane >> 4) & 1) * 8;

    float acc1[2][4][4] = {}, acc2[2][4][4] = {};

    auto issue = [&](int k0, int st) {
        cp16(&As1[st][ar * 40 + ac], d_phw + (size_t)(m0 + ar) * 256 + k0 + ac);
        cp16(&As2[st][ar * 40 + ac], d_gw + (size_t)(m0 + ar) * 256 + k0 + ac);
        cp16(&Bs[st][br * 136 + bc], Xbf + (size_t)(k0 + br) * NSP + n0 + bc);
        cp16(&Bs[st][br * 136 + bc + 64], Xbf + (size_t)(k0 + br) * NSP + n0 + bc + 64);
    };

    issue(0, 0); CP_COMMIT();
    issue(32, 1); CP_COMMIT();

    for (int i = 0; i < 8; i++) {
        CP_WAIT1();
        __syncthreads();
        int kn = (i + 2) * 32;
        if (kn < 256) issue(kn, (i + 2) % 3);
        CP_COMMIT();
        const int st = i % 3;
#pragma unroll
        for (int kk = 0; kk < 32; kk += 16) {
            uint32_t a1[2][4], a2[2][4], bb[2][4];
#pragma unroll
            for (int ma = 0; ma < 2; ma++) {
                int rb = wm * 32 + ma * 16;
                ldsm4(a1[ma], &As1[st][(rb + a_row) * 40 + kk + a_col]);
                ldsm4(a2[ma], &As2[st][(rb + a_row) * 40 + kk + a_col]);
            }
#pragma unroll
            for (int pr = 0; pr < 2; pr++)
                ldsm4t(bb[pr], &Bs[st][(kk + bt_kr) * 136 + wn * 32 + pr * 16 + bt_nc]);
#pragma unroll
            for (int ma = 0; ma < 2; ma++)
#pragma unroll
                for (int na = 0; na < 4; na++) {
                    uint32_t b0 = bb[na >> 1][(na & 1) * 2];
                    uint32_t b1 = bb[na >> 1][(na & 1) * 2 + 1];
                    mma_bf16(acc1[ma][na], a1[ma], b0, b1);
                    mma_bf16(acc2[ma][na], a2[ma], b0, b1);
                }
        }
    }

    bf16* C1 = d_Tph + (size_t)bz * C_MID * NSP;
    bf16* C2 = d_Tg + (size_t)bz * C_MID * NSP;
#pragma unroll
    for (int ma = 0; ma < 2; ma++) {
        int rm = m0 + wm * 32 + ma * 16 + gq;
#pragma unroll
        for (int na = 0; na < 4; na++) {
            int cn = n0 + wn * 32 + na * 8 + 2 * tg;
            *(bf162*)(C1 + (size_t)rm * NSP + cn) =
                __floats2bfloat162_rn(acc1[ma][na][0], acc1[ma][na][1]);
            *(bf162*)(C1 + (size_t)(rm + 8) * NSP + cn) =
                __floats2bfloat162_rn(acc1[ma][na][2], acc1[ma][na][3]);
            *(bf162*)(C2 + (size_t)rm * NSP + cn) =
                __floats2bfloat162_rn(acc2[ma][na][0], acc2[ma][na][1]);
            *(bf162*)(C2 + (size_t)(rm + 8) * NSP + cn) =
                __floats2bfloat162_rn(acc2[ma][na][2], acc2[ma][na][3]);
        }
    }
}

// ---------------------------------------------------------------------------
// bsm: Mraw = Tg @ Tph^T (NT bf16, split-K=8, cp.async 3-stage) + row sums
// grid (4, 8, 4)
// ---------------------------------------------------------------------------
__global__ void __launch_bounds__(256) bsm() {
    __shared__ bf16 As[3][64 * 40], Bs[3][64 * 40];
    const int ti = blockIdx.x >> 1, tj = blockIdx.x & 1;
    const int i0 = ti * 64, j0 = tj * 64;
    const int kb = blockIdx.y * 512;
    const int bz = blockIdx.z;
    const bf16* A = d_Tg + (size_t)bz * C_MID * NSP;
    const bf16* B = d_Tph + (size_t)bz * C_MID * NSP;

    const int tid = threadIdx.x;
    const int lane = tid & 31, warp = tid >> 5;
    const int wm = warp >> 2, wn = warp & 3;
    const int gq = lane >> 2, tg = lane & 3;
    const int lr = tid >> 2, lc = (tid & 3) * 8;
    const int a_row = (lane & 7) + ((lane >> 3) & 1) * 8;
    const int a_col = (lane >> 4) * 8;
    const int b_nr = (lane & 7) + ((lane >> 4) & 1) * 8;
    const int b_kc = ((lane >> 3) & 1) * 8;

    float acc[2][2][4] = {};
    float sa = 0.f, sb = 0.f;
    const bool dosum = (ti == tj);

    auto issue = [&](int k0, int st) {
        cp16(&As[st][lr * 40 + lc], A + (size_t)(i0 + lr) * NSP + kb + k0 + lc);
        cp16(&Bs[st][lr * 40 + lc], B + (size_t)(j0 + lr) * NSP + kb + k0 + lc);
    };

    issue(0, 0); CP_COMMIT();
    issue(32, 1); CP_COMMIT();

    for (int i = 0; i < 16; i++) {
        CP_WAIT1();
        __syncthreads();
        int kn = (i + 2) * 32;
        if (kn < 512) issue(kn, (i + 2) % 3);
        CP_COMMIT();
        const int st = i % 3;
        if (dosum) {
            sa += sum8bf(*(const uint4*)&As[st][lr * 40 + lc]);
            sb += sum8bf(*(const uint4*)&Bs[st][lr * 40 + lc]);
        }
#pragma unroll
        for (int kk = 0; kk < 32; kk += 16) {
            uint32_t a[2][4], bbv[4];
#pragma unroll
            for (int ma = 0; ma < 2; ma++)
                ldsm4(a[ma], &As[st][(wm * 32 + ma * 16 + a_row) * 40 + kk + a_col]);
            ldsm4(bbv, &Bs[st][(wn * 16 + b_nr) * 40 + kk + b_kc]);
#pragma unroll
            for (int ma = 0; ma < 2; ma++) {
                mma_bf16(acc[ma][0], a[ma], bbv[0], bbv[1]);
                mma_bf16(acc[ma][1], a[ma], bbv[2], bbv[3]);
            }
        }
    }

    float* Mp = d_M + (size_t)bz * C_MID * C_MID;
#pragma unroll
    for (int ma = 0; ma < 2; ma++) {
        int rr = i0 + wm * 32 + ma * 16 + gq;
#pragma unroll
        for (int na = 0; na < 2; na++) {
            int cn = j0 + wn * 16 + na * 8 + 2 * tg;
            atomicAdd(&Mp[(size_t)rr * C_MID + cn],           acc[ma][na][0]);
            atomicAdd(&Mp[(size_t)rr * C_MID + cn + 1],       acc[ma][na][1]);
            atomicAdd(&Mp[(size_t)(rr + 8) * C_MID + cn],     acc[ma][na][2]);
            atomicAdd(&Mp[(size_t)(rr + 8) * C_MID + cn + 1], acc[ma][na][3]);
        }
    }
    if (dosum) {
        sa += __shfl_xor_sync(0xffffffffu, sa, 1);
        sa += __shfl_xor_sync(0xffffffffu, sa, 2);
        sb += __shfl_xor_sync(0xffffffffu, sb, 1);
        sb += __shfl_xor_sync(0xffffffffu, sb, 2);
        if ((tid & 3) == 0) {
            atomicAdd(&d_gs[bz * C_MID + i0 + lr], sa);
            atomicAdd(&d_ws[bz * C_MID + j0 + lr], sb);
        }
    }
}

// ---------------------------------------------------------------------------
// wfold: Wfull = out_w_bf @ Mfold_bf (rank-1 fused at B load).
// 64x64 tile, K=128 single-shot smem, ONE barrier. grid (2, 4, 4)
// ---------------------------------------------------------------------------
__global__ void __launch_bounds__(256) wfold(const float* __restrict__ g_b,
                                             const float* __restrict__ phi_b) {
    __shared__ bf16 As[64 * 136];   // out_w rows i0..i0+64, K=128
    __shared__ bf16 Bs[128 * 72];   // Mfold[k][j0..j0+64]
    __shared__ float pbs[C_MID], wss[C_MID];

    const int bz = blockIdx.z;
    const int i0 = blockIdx.y * 64;
    const int j0 = blockIdx.x * 64;

    const int tid = threadIdx.x;
    const int lane = tid & 31, warp = tid >> 5;
    const int wm = warp >> 2, wn = warp & 3;
    const int gq = lane >> 2, tg = lane & 3;
    const int a_row = (lane & 7) + ((lane >> 3) & 1) * 8;
    const int a_col = (lane >> 4) * 8;
    const int bt_kr = (lane & 7) + ((lane >> 3) & 1) * 8;
    const int bt_nc = ((lane >> 4) & 1) * 8;

    if (tid < 128) {
        pbs[tid] = phi_b[tid];
        wss[tid] = d_ws[bz * C_MID + tid];
    }

    // load As: out_w bf16 [i0+row][0:128]
    {
        int arow = tid >> 2, acb = (tid & 3) * 32;
#pragma unroll
        for (int i = 0; i < 4; i++)
            *(uint4*)&As[arow * 136 + acb + i * 8] =
                *(const uint4*)(d_ow + (size_t)(i0 + arow) * C_MID + acb + i * 8);
    }
    __syncthreads();   // pbs/wss ready before fusion

    // load Bs: Mfold[k][j0+c] with rank-1 fusion, fp32 -> bf16
    {
        int brow = tid >> 1, bcb = (tid & 1) * 32;
        const float gsv = d_gs[bz * C_MID + brow];
        const float gbv = g_b[brow];
        const float* Mrow = d_M + (size_t)bz * C_MID * C_MID + (size_t)brow * C_MID + j0;
#pragma unroll
        for (int i = 0; i < 8; i++) {
            int c = bcb + i * 4;
            float4 mr = *(const float4*)(Mrow + c);
            float4 pb = *(const float4*)&pbs[j0 + c];
            float4 wv = *(const float4*)&wss[j0 + c];
            float4 v;
            v.x = mr.x + gsv * pb.x + gbv * (wv.x + 4096.f * pb.x);
            v.y = mr.y + gsv * pb.y + gbv * (wv.y + 4096.f * pb.y);
            v.z = mr.z + gsv * pb.z + gbv * (wv.z + 4096.f * pb.z);
            v.w = mr.w + gsv * pb.w + gbv * (wv.w + 4096.f * pb.w);
            *(uint2*)&Bs[brow * 72 + c] = f4_to_bf(v);
        }
    }
    __syncthreads();

    float acc[2][2][4] = {};
#pragma unroll
    for (int kk = 0; kk < 128; kk += 16) {
        uint32_t a[2][4], bb[4];
#pragma unroll
        for (int ma = 0; ma < 2; ma++)
            ldsm4(a[ma], &As[(wm * 32 + ma * 16 + a_row) * 136 + kk + a_col]);
        ldsm4t(bb, &Bs[(kk + bt_kr) * 72 + wn * 16 + bt_nc]);
#pragma unroll
        for (int ma = 0; ma < 2; ma++) {
            mma_bf16(acc[ma][0], a[ma], bb[0], bb[1]);
            mma_bf16(acc[ma][1], a[ma], bb[2], bb[3]);
        }
    }

    float* W = d_W + (size_t)bz * C_IN * C_MID;
#pragma unroll
    for (int ma = 0; ma < 2; ma++) {
        int rm = i0 + wm * 32 + ma * 16 + gq;
#pragma unroll
        for (int na = 0; na < 2; na++) {
            int cn = j0 + wn * 16 + na * 8 + 2 * tg;
            *(float2*)(W + (size_t)rm * C_MID + cn) = make_float2(acc[ma][na][0], acc[ma][na][1]);
            *(float2*)(W + (size_t)(rm + 8) * C_MID + cn) = make_float2(acc[ma][na][2], acc[ma][na][3]);
        }
    }
}

// ---------------------------------------------------------------------------
// afold2: Af = Wfull @ theta_w_bf * INVN (bf16 out), + cvec (n0==0 CTAs).
// A loaded once (bf16), B in 2 k-chunks; 3 barriers. grid (2, 4, 4)
// ---------------------------------------------------------------------------
__global__ void __launch_bounds__(256) afold2(const float* __restrict__ theta_b,
                                              const float* __restrict__ out_b) {
    __shared__ bf16 As[64 * 136];   // Wfull rows m0..+64, K=128 (bf16)
    __shared__ bf16 Bs[64 * 136];   // theta_w k-chunk of 64 x 128 cols
    __shared__ float tbs[C_MID];

    const int bz = blockIdx.z;
    const int m0 = blockIdx.y * 64;
    const int n0 = blockIdx.x * 128;

    const int tid = threadIdx.x;
    const int lane = tid & 31, warp = tid >> 5;
    const int wm = warp >> 2, wn = warp & 3;
    const int gq = lane >> 2, tg = lane & 3;
    const int a_row = (lane & 7) + ((lane >> 3) & 1) * 8;
    const int a_col = (lane >> 4) * 8;
    const int bt_kr = (lane & 7) + ((lane >> 3) & 1) * 8;
    const int bt_nc = ((lane >> 4) & 1) * 8;

    if (tid < 128) tbs[tid] = theta_b[tid];

    // load As: Wfull fp32 -> bf16
    {
        int arow = tid >> 2, acb = (tid & 3) * 32;
        const float* Wr = d_W + (size_t)bz * C_IN * C_MID + (size_t)(m0 + arow) * C_MID;
#pragma unroll
        for (int i = 0; i < 8; i++)
            *(uint2*)&As[arow * 136 + acb + i * 4] = f4_to_bf(*(const float4*)(Wr + acb + i * 4));
    }

    float acc[2][4][4] = {};
    const int brow = tid >> 2, bcb = (tid & 3) * 32;

#pragma unroll
    for (int h = 0; h < 2; h++) {
        __syncthreads();   // As ready (h=0) / Bs reuse safe (h=1)
#pragma unroll
        for (int i = 0; i < 4; i++)
            *(uint4*)&Bs[brow * 136 + bcb + i * 8] =
                *(const uint4*)(d_thw + (size_t)(h * 64 + brow) * C_IN + n0 + bcb + i * 8);
        __syncthreads();
#pragma unroll
        for (int kk2 = 0; kk2 < 64; kk2 += 16) {
            uint32_t a[2][4], bb[2][4];
#pragma unroll
            for (int ma = 0; ma < 2; ma++)
                ldsm4(a[ma], &As[(wm * 32 + ma * 16 + a_row) * 136 + h * 64 + kk2 + a_col]);
#pragma unroll
            for (int pr = 0; pr < 2; pr++)
                ldsm4t(bb[pr], &Bs[(kk2 + bt_kr) * 136 + wn * 32 + pr * 16 + bt_nc]);
#pragma unroll
            for (int ma = 0; ma < 2; ma++)
#pragma unroll
                for (int na = 0; na < 4; na++)
                    mma_bf16(acc[ma][na], a[ma],
                             bb[na >> 1][(na & 1) * 2], bb[na >> 1][(na & 1) * 2 + 1]);
        }
    }

    bf16* Af = d_Af + (size_t)bz * C_IN * C_IN;
#pragma unroll
    for (int ma = 0; ma < 2; ma++) {
        int rm = m0 + wm * 32 + ma * 16 + gq;
#pragma unroll
        for (int na = 0; na < 4; na++) {
            int cn = n0 + wn * 32 + na * 8 + 2 * tg;
            *(bf162*)(Af + (size_t)rm * C_IN + cn) =
                __floats2bfloat162_rn(acc[ma][na][0] * INVN, acc[ma][na][1] * INVN);
            *(bf162*)(Af + (size_t)(rm + 8) * C_IN + cn) =
                __floats2bfloat162_rn(acc[ma][na][2] * INVN, acc[ma][na][3] * INVN);
        }
    }

    // cvec = (Wm row . theta_b)/N + out_b   (reads As bf16, untouched since load)
    if (blockIdx.x == 0) {
        int r = warp * 8;
#pragma unroll
        for (int d = 0; d < 8; d++) {
            uint2 w2 = *(const uint2*)&As[(r + d) * 136 + lane * 4];
            const bf162* pp = (const bf162*)&w2;
            float2 f0 = __bfloat1622float2(pp[0]);
            float2 f1 = __bfloat1622float2(pp[1]);
            float a = f0.x * tbs[lane * 4] + f0.y * tbs[lane * 4 + 1]
                    + f1.x * tbs[lane * 4 + 2] + f1.y * tbs[lane * 4 + 3];
#pragma unroll
            for (int o = 16; o; o >>= 1) a += __shfl_xor_sync(0xffffffffu, a, o);
            if (lane == 0) d_cvec[bz * C_IN + m0 + r + d] = a * INVN + out_b[m0 + r + d];
        }
    }
}

// ---------------------------------------------------------------------------
// final: out = Af @ Xbf + X + cvec  (bf16, cp.async 3-stage). grid (32, 4, 4)
// ---------------------------------------------------------------------------
__global__ void __launch_bounds__(256) final_k(const float* __restrict__ x,
                                               float* __restrict__ out) {
    __shared__ bf16 As[3][64 * 40], Bs[3][32 * 136];
    const int bz = blockIdx.z;
    const int m0 = blockIdx.y * 64;
    const int n0 = blockIdx.x * 128;
    const bf16* A = d_Af + (size_t)bz * C_IN * C_IN;
    const bf16* Xb16 = d_Xbf + (size_t)bz * C_IN * NSP;
    const float* Xb = x + (size_t)bz * C_IN * NSP;
    float* Ob = out + (size_t)bz * C_IN * NSP;

    const int tid = threadIdx.x;
    const int lane = tid & 31, warp = tid >> 5;
    const int wm = warp >> 2, wn = warp & 3;
    const int gq = lane >> 2, tg = lane & 3;
    const int ar = tid >> 2, ac = (tid & 3) * 8;
    const int br = tid >> 3, bc = (tid & 7) * 8;
    const int a_row = (lane & 7) + ((lane >> 3) & 1) * 8;
    const int a_col = (lane >> 4) * 8;
    const int bt_kr = (lane & 7) + ((lane >> 3) & 1) * 8;
    const int bt_nc = ((lane >> 4) & 1) * 8;

    float acc[2][4][4] = {};

    auto issue = [&](int k0, int st) {
        cp16(&As[st][ar * 40 + ac], A + (size_t)(m0 + ar) * C_IN + k0 + ac);
        cp16(&Bs[st][br * 136 + bc], Xb16 + (size_t)(k0 + br) * NSP + n0 + bc);
        cp16(&Bs[st][br * 136 + bc + 64], Xb16 + (size_t)(k0 + br) * NSP + n0 + bc + 64);
    };

    issue(0, 0); CP_COMMIT();
    issue(32, 1); CP_COMMIT();

    for (int i = 0; i < 8; i++) {
        CP_WAIT1();
        __syncthreads();
        int kn = (i + 2) * 32;
        if (kn < 256) issue(kn, (i + 2) % 3);
        CP_COMMIT();
        const int st = i % 3;
#pragma unroll
        for (int kk = 0; kk < 32; kk += 16) {
            uint32_t a[2][4], bb[2][4];
#pragma unroll
            for (int ma = 0; ma < 2; ma++)
                ldsm4(a[ma], &As[st][(wm * 32 + ma * 16 + a_row) * 40 + kk + a_col]);
#pragma unroll
            for (int pr = 0; pr < 2; pr++)
                ldsm4t(bb[pr], &Bs[st][(kk + bt_kr) * 136 + wn * 32 + pr * 16 + bt_nc]);
#pragma unroll
            for (int ma = 0; ma < 2; ma++)
#pragma unroll
                for (int na = 0; na < 4; na++)
                    mma_bf16(acc[ma][na], a[ma],
                             bb[na >> 1][(na & 1) * 2], bb[na >> 1][(na & 1) * 2 + 1]);
        }
    }

    const float* cb = d_cvec + bz * C_IN;
#pragma unroll
    for (int ma = 0; ma < 2; ma++) {
        int rm = m0 + wm * 32 + ma * 16 + gq;
        float c0 = cb[rm], c1 = cb[rm + 8];
#pragma unroll
        for (int na = 0; na < 4; na++) {
            int cn = n0 + wn * 32 + na * 8 + 2 * tg;
            float2 x0 = *(const float2*)(Xb + (size_t)rm * NSP + cn);
            float2 x1 = *(const float2*)(Xb + (size_t)(rm + 8) * NSP + cn);
            *(float2*)(Ob + (size_t)rm * NSP + cn) =
                make_float2(acc[ma][na][0] + x0.x + c0, acc[ma][na][1] + x0.y + c0);
            *(float2*)(Ob + (size_t)(rm + 8) * NSP + cn) =
                make_float2(acc[ma][na][2] + x1.x + c1, acc[ma][na][3] + x1.y + c1);
        }
    }
}

// ---------------------------------------------------------------------------
// Host launcher — 6 kernels
// ---------------------------------------------------------------------------
extern "C" void kernel_launch(void* const* d_in, const int* in_sizes, int n_in,
                              void* d_out, int out_size) {
    const float* x       = (const float*)d_in[0];
    const float* g_w     = (const float*)d_in[1];
    const float* g_b     = (const float*)d_in[2];
    const float* theta_w = (const float*)d_in[3];
    const float* theta_b = (const float*)d_in[4];
    const float* phi_w   = (const float*)d_in[5];
    const float* phi_b   = (const float*)d_in[6];
    const float* out_w   = (const float*)d_in[7];
    const float* out_b   = (const float*)d_in[8];
    float* out = (float*)d_out;

    convert_init<<<297, 256>>>(x, phi_w, g_w, theta_w, out_w);
    proj<<<dim3(32, 2, 4), 256>>>();
    bsm<<<dim3(4, 8, 4), 256>>>();
    wfold<<<dim3(2, 4, 4), 256>>>(g_b, phi_b);
    afold2<<<dim3(2, 4, 4), 256>>>(theta_b, out_b);
    final_k<<<dim3(32, 4, 4), 256>>>(x, out);
}